// round 1
// baseline (speedup 1.0000x reference)
#include <cuda_runtime.h>
#include <math.h>

#define N_NODES 100000
#define N_EDGES 1600000
#define DIN 64
#define DHID 128
#define DOUT 40
#define SCAN_B 512
#define SCAN_NB ((N_NODES + SCAN_B - 1) / SCAN_B)

// ---------------- device scratch (no allocations allowed) ----------------
__device__ int g_is64;
__device__ int g_deg[N_NODES];
__device__ int g_rowptr[N_NODES + 1];
__device__ int g_fill[N_NODES];
__device__ int g_col[N_EDGES];
__device__ int g_part[SCAN_NB];
__device__ float g_agg1[(size_t)N_NODES * DIN];
__device__ float g_h1[(size_t)N_NODES * DHID];
__device__ float g_agg2[(size_t)N_NODES * DHID];

// ---------------- edge index access (int64 or int32, runtime-detected) ----
__device__ __forceinline__ int esrc(const void* ei, int e) {
    return g_is64 ? (int)((const long long*)ei)[e] : ((const int*)ei)[e];
}
__device__ __forceinline__ int edst(const void* ei, int e) {
    return g_is64 ? (int)((const long long*)ei)[(size_t)N_EDGES + e]
                  : ((const int*)ei)[(size_t)N_EDGES + e];
}

// If data is int64 (values < 1e5), every odd 32-bit word of the src region is 0.
__global__ void k_detect(const int* ei) {
    bool ok = true;
    for (int i = threadIdx.x; i < 4096; i += blockDim.x)
        if (ei[2 * i + 1] != 0) ok = false;
    int all = __syncthreads_and((int)ok);
    if (threadIdx.x == 0) g_is64 = all ? 1 : 0;
}

__global__ void k_init_deg() {
    int i = blockIdx.x * blockDim.x + threadIdx.x;
    if (i < N_NODES) g_deg[i] = 0;
}

__global__ void k_hist(const void* ei) {
    int e = blockIdx.x * blockDim.x + threadIdx.x;
    if (e < N_EDGES) atomicAdd(&g_deg[edst(ei, e)], 1);
}

__global__ void k_scan_block() {
    __shared__ int s[SCAN_B];
    int i = blockIdx.x * SCAN_B + threadIdx.x;
    int v = (i < N_NODES) ? g_deg[i] : 0;
    s[threadIdx.x] = v;
    __syncthreads();
    for (int off = 1; off < SCAN_B; off <<= 1) {
        int t = (threadIdx.x >= off) ? s[threadIdx.x - off] : 0;
        __syncthreads();
        s[threadIdx.x] += t;
        __syncthreads();
    }
    if (i < N_NODES) g_rowptr[i] = s[threadIdx.x] - v;  // exclusive
    if (threadIdx.x == SCAN_B - 1) g_part[blockIdx.x] = s[SCAN_B - 1];
}

__global__ void k_scan_part() {
    int run = 0;
    for (int b = 0; b < SCAN_NB; b++) {
        int v = g_part[b];
        g_part[b] = run;
        run += v;
    }
}

__global__ void k_scan_add() {
    int i = blockIdx.x * blockDim.x + threadIdx.x;
    if (i < N_NODES) {
        int r = g_rowptr[i] + g_part[i / SCAN_B];
        g_rowptr[i] = r;
        g_fill[i] = r;
    }
    if (i == 0) g_rowptr[N_NODES] = N_EDGES;
}

__global__ void k_scatter(const void* ei) {
    int e = blockIdx.x * blockDim.x + threadIdx.x;
    if (e < N_EDGES) {
        int d = edst(ei, e);
        int p = atomicAdd(&g_fill[d], 1);
        g_col[p] = esrc(ei, e);
    }
}

// ---------------- mean aggregation: one warp per node ----------------
__global__ void k_agg1(const float* __restrict__ x) {
    int warp = (blockIdx.x * blockDim.x + threadIdx.x) >> 5;
    int lane = threadIdx.x & 31;
    if (warp >= N_NODES) return;
    float a0 = 0.f, a1 = 0.f;
    int s0 = g_rowptr[warp], s1 = g_rowptr[warp + 1];
    for (int e = s0; e < s1; e++) {
        const float* f = x + (size_t)g_col[e] * DIN;
        a0 += f[lane];
        a1 += f[lane + 32];
    }
    float inv = 1.f / (float)max(s1 - s0, 1);
    g_agg1[(size_t)warp * DIN + lane] = a0 * inv;
    g_agg1[(size_t)warp * DIN + lane + 32] = a1 * inv;
}

__global__ void k_agg2() {
    int warp = (blockIdx.x * blockDim.x + threadIdx.x) >> 5;
    int lane = threadIdx.x & 31;
    if (warp >= N_NODES) return;
    float a0 = 0.f, a1 = 0.f, a2 = 0.f, a3 = 0.f;
    int s0 = g_rowptr[warp], s1 = g_rowptr[warp + 1];
    for (int e = s0; e < s1; e++) {
        const float* f = g_h1 + (size_t)g_col[e] * DHID;
        a0 += f[lane];
        a1 += f[lane + 32];
        a2 += f[lane + 64];
        a3 += f[lane + 96];
    }
    float inv = 1.f / (float)max(s1 - s0, 1);
    size_t b = (size_t)warp * DHID;
    g_agg2[b + lane] = a0 * inv;
    g_agg2[b + lane + 32] = a1 * inv;
    g_agg2[b + lane + 64] = a2 * inv;
    g_agg2[b + lane + 96] = a3 * inv;
}

// ---------------- layer 1: h1 = relu(agg1 @ W1l^T + b1 + x @ W1r^T) -------
// Combined 128-dim input [agg1|x] vs combined weight; SMEM-cached weights,
// o-major with padded rows (stride 132 -> bank stride 4: LDS.128 conflict-free).
#define L1_WARPS 8
#define L1_ND 3
#define L1_ITER 4
#define L1_NPB (L1_WARPS * L1_ND * L1_ITER)  // 96 nodes per block
#define L1_WPAD 132

__global__ void k_lin1(const float* __restrict__ x,
                       const float* __restrict__ W1l,
                       const float* __restrict__ W1r,
                       const float* __restrict__ b1) {
    __shared__ float sW[64][L1_WPAD];                 // 33792 B
    __shared__ float sIn[L1_WARPS][L1_ND][DHID];      // 12288 B
    int tid = threadIdx.x;
    int half = blockIdx.y;  // output halves 0..63 / 64..127
    for (int idx = tid; idx < 64 * DHID; idx += blockDim.x) {
        int o = idx >> 7, k = idx & 127;
        int og = half * 64 + o;
        sW[o][k] = (k < DIN) ? W1l[og * DIN + k] : W1r[og * DIN + (k - DIN)];
    }
    __syncthreads();
    int w = tid >> 5, lane = tid & 31;
    int o0 = half * 64 + lane;  // this lane's outputs: o0 and o0+32
    float bb0 = b1[o0], bb1 = b1[o0 + 32];

    for (int it = 0; it < L1_ITER; it++) {
        int nodeBase = blockIdx.x * L1_NPB + (w * L1_ITER + it) * L1_ND;
#pragma unroll
        for (int nd = 0; nd < L1_ND; nd++) {
            int n = nodeBase + nd;
            if (n < N_NODES) {
                for (int t = lane; t < DHID; t += 32)
                    sIn[w][nd][t] = (t < DIN) ? g_agg1[(size_t)n * DIN + t]
                                              : x[(size_t)n * DIN + (t - DIN)];
            }
        }
        __syncwarp();
        float acc[L1_ND][2];
#pragma unroll
        for (int nd = 0; nd < L1_ND; nd++) { acc[nd][0] = bb0; acc[nd][1] = bb1; }
#pragma unroll 4
        for (int k = 0; k < DHID; k += 4) {
            float4 w0 = *(const float4*)&sW[lane][k];
            float4 w1 = *(const float4*)&sW[lane + 32][k];
#pragma unroll
            for (int nd = 0; nd < L1_ND; nd++) {
                float4 vk = *(const float4*)&sIn[w][nd][k];
                acc[nd][0] = fmaf(w0.x, vk.x, acc[nd][0]);
                acc[nd][0] = fmaf(w0.y, vk.y, acc[nd][0]);
                acc[nd][0] = fmaf(w0.z, vk.z, acc[nd][0]);
                acc[nd][0] = fmaf(w0.w, vk.w, acc[nd][0]);
                acc[nd][1] = fmaf(w1.x, vk.x, acc[nd][1]);
                acc[nd][1] = fmaf(w1.y, vk.y, acc[nd][1]);
                acc[nd][1] = fmaf(w1.z, vk.z, acc[nd][1]);
                acc[nd][1] = fmaf(w1.w, vk.w, acc[nd][1]);
            }
        }
#pragma unroll
        for (int nd = 0; nd < L1_ND; nd++) {
            int n = nodeBase + nd;
            if (n < N_NODES) {
                float r0 = acc[nd][0], r1 = acc[nd][1];
                g_h1[(size_t)n * DHID + o0] = r0 > 0.f ? r0 : 0.f;
                g_h1[(size_t)n * DHID + o0 + 32] = r1 > 0.f ? r1 : 0.f;
            }
        }
        __syncwarp();
    }
}

// ---------------- layer 2 + log_softmax --------------------------------
// out = log_softmax(agg2 @ W2l^T + b2 + h1 @ W2r^T). Combined 256-dim input.
// Lane computes outputs o=lane (0..31) and o=32+lane (lane<8).
#define L2_WARPS 2
#define L2_ND 3
#define L2_ITER 8
#define L2_NPB (L2_WARPS * L2_ND * L2_ITER)  // 48 nodes per block
#define L2_WPAD 260

__global__ void k_lin2(const float* __restrict__ W2l,
                       const float* __restrict__ W2r,
                       const float* __restrict__ b2,
                       float* __restrict__ out) {
    __shared__ float sW[DOUT][L2_WPAD];                   // 41600 B
    __shared__ float sIn[L2_WARPS][L2_ND][2 * DHID];      // 6144 B
    int tid = threadIdx.x;
    for (int idx = tid; idx < DOUT * 256; idx += blockDim.x) {
        int o = idx >> 8, k = idx & 255;
        sW[o][k] = (k < DHID) ? W2l[o * DHID + k] : W2r[o * DHID + (k - DHID)];
    }
    __syncthreads();
    int w = tid >> 5, lane = tid & 31;
    float bb0 = b2[lane];
    float bb1 = (lane < 8) ? b2[32 + lane] : 0.f;

    for (int it = 0; it < L2_ITER; it++) {
        int nodeBase = blockIdx.x * L2_NPB + (w * L2_ITER + it) * L2_ND;
#pragma unroll
        for (int nd = 0; nd < L2_ND; nd++) {
            int n = nodeBase + nd;
            if (n < N_NODES) {
                for (int t = lane; t < 2 * DHID; t += 32)
                    sIn[w][nd][t] = (t < DHID) ? g_agg2[(size_t)n * DHID + t]
                                               : g_h1[(size_t)n * DHID + (t - DHID)];
            }
        }
        __syncwarp();
        float acc[L2_ND][2];
#pragma unroll
        for (int nd = 0; nd < L2_ND; nd++) { acc[nd][0] = bb0; acc[nd][1] = bb1; }
#pragma unroll 4
        for (int k = 0; k < 2 * DHID; k += 4) {
            float4 w0 = *(const float4*)&sW[lane][k];
            float4 w1 = make_float4(0.f, 0.f, 0.f, 0.f);
            if (lane < 8) w1 = *(const float4*)&sW[32 + lane][k];
#pragma unroll
            for (int nd = 0; nd < L2_ND; nd++) {
                float4 vk = *(const float4*)&sIn[w][nd][k];
                acc[nd][0] = fmaf(w0.x, vk.x, acc[nd][0]);
                acc[nd][0] = fmaf(w0.y, vk.y, acc[nd][0]);
                acc[nd][0] = fmaf(w0.z, vk.z, acc[nd][0]);
                acc[nd][0] = fmaf(w0.w, vk.w, acc[nd][0]);
                acc[nd][1] = fmaf(w1.x, vk.x, acc[nd][1]);
                acc[nd][1] = fmaf(w1.y, vk.y, acc[nd][1]);
                acc[nd][1] = fmaf(w1.z, vk.z, acc[nd][1]);
                acc[nd][1] = fmaf(w1.w, vk.w, acc[nd][1]);
            }
        }
#pragma unroll
        for (int nd = 0; nd < L2_ND; nd++) {
            int n = nodeBase + nd;
            float a0 = acc[nd][0];
            float a1 = (lane < 8) ? acc[nd][1] : -INFINITY;
            float m = fmaxf(a0, a1);
            for (int off = 16; off; off >>= 1)
                m = fmaxf(m, __shfl_xor_sync(0xffffffffu, m, off));
            float s = expf(a0 - m) + ((lane < 8) ? expf(a1 - m) : 0.f);
            for (int off = 16; off; off >>= 1)
                s += __shfl_xor_sync(0xffffffffu, s, off);
            float lse = m + logf(s);
            if (n < N_NODES) {
                out[(size_t)n * DOUT + lane] = a0 - lse;
                if (lane < 8) out[(size_t)n * DOUT + 32 + lane] = a1 - lse;
            }
        }
        __syncwarp();
    }
}

// ---------------- launch --------------------------------------------------
extern "C" void kernel_launch(void* const* d_in, const int* in_sizes, int n_in,
                              void* d_out, int out_size) {
    const float* x = (const float*)d_in[0];
    const void* ei = d_in[1];
    const float* W1l = (const float*)d_in[2];
    const float* b1 = (const float*)d_in[3];
    const float* W1r = (const float*)d_in[4];
    const float* W2l = (const float*)d_in[5];
    const float* b2 = (const float*)d_in[6];
    const float* W2r = (const float*)d_in[7];
    float* out = (float*)d_out;

    k_detect<<<1, 256>>>((const int*)ei);
    k_init_deg<<<(N_NODES + 255) / 256, 256>>>();
    k_hist<<<(N_EDGES + 255) / 256, 256>>>(ei);
    k_scan_block<<<SCAN_NB, SCAN_B>>>();
    k_scan_part<<<1, 1>>>();
    k_scan_add<<<(N_NODES + 255) / 256, 256>>>();
    k_scatter<<<(N_EDGES + 255) / 256, 256>>>(ei);

    // layer 1
    k_agg1<<<(N_NODES * 32 + 255) / 256, 256>>>(x);
    dim3 g1((N_NODES + L1_NPB - 1) / L1_NPB, 2);
    k_lin1<<<g1, 256>>>(x, W1l, W1r, b1);

    // layer 2 + log_softmax
    k_agg2<<<(N_NODES * 32 + 255) / 256, 256>>>();
    k_lin2<<<(N_NODES + L2_NPB - 1) / L2_NPB, L2_WARPS * 32>>>(W2l, W2r, b2, out);
}

// round 2
// speedup vs baseline: 1.9743x; 1.9743x over previous
#include <cuda_runtime.h>
#include <math.h>

#define N_NODES 100000
#define N_EDGES 1600000
#define DIN 64
#define DHID 128
#define DOUT 40
#define SCAN_B 512
#define SCAN_NB ((N_NODES + SCAN_B - 1) / SCAN_B)

// ---------------- device scratch (no allocations allowed) ----------------
__device__ int g_is64;
__device__ int g_deg[N_NODES];
__device__ int g_rowptr[N_NODES + 1];
__device__ int g_fill[N_NODES];
__device__ int g_col[N_EDGES];
__device__ int g_part[256];
__device__ float g_agg1[(size_t)N_NODES * DIN];
__device__ float g_h1[(size_t)N_NODES * DHID];
__device__ float g_y2l[(size_t)N_NODES * DOUT];
__device__ float g_y2r[(size_t)N_NODES * DOUT];

// ---------------- edge index access (int64 or int32, runtime-detected) ----
__device__ __forceinline__ int esrc(const void* ei, int e) {
    return g_is64 ? (int)((const long long*)ei)[e] : ((const int*)ei)[e];
}
__device__ __forceinline__ int edst(const void* ei, int e) {
    return g_is64 ? (int)((const long long*)ei)[(size_t)N_EDGES + e]
                  : ((const int*)ei)[(size_t)N_EDGES + e];
}

// If data is int64 (values < 1e5), every odd 32-bit word of the src region is 0.
__global__ void k_detect(const int* ei) {
    bool ok = true;
    for (int i = threadIdx.x; i < 4096; i += blockDim.x)
        if (ei[2 * i + 1] != 0) ok = false;
    int all = __syncthreads_and((int)ok);
    if (threadIdx.x == 0) g_is64 = all ? 1 : 0;
}

__global__ void k_init_deg() {
    int i = blockIdx.x * blockDim.x + threadIdx.x;
    if (i < N_NODES) g_deg[i] = 0;
}

__global__ void k_hist(const void* ei) {
    int e = blockIdx.x * blockDim.x + threadIdx.x;
    if (e < N_EDGES) atomicAdd(&g_deg[edst(ei, e)], 1);
}

__global__ void k_scan_block() {
    __shared__ int s[SCAN_B];
    int i = blockIdx.x * SCAN_B + threadIdx.x;
    int v = (i < N_NODES) ? g_deg[i] : 0;
    s[threadIdx.x] = v;
    __syncthreads();
    for (int off = 1; off < SCAN_B; off <<= 1) {
        int t = (threadIdx.x >= off) ? s[threadIdx.x - off] : 0;
        __syncthreads();
        s[threadIdx.x] += t;
        __syncthreads();
    }
    if (i < N_NODES) g_rowptr[i] = s[threadIdx.x] - v;  // exclusive
    if (threadIdx.x == SCAN_B - 1) g_part[blockIdx.x] = s[SCAN_B - 1];
}

// single-block parallel scan over SCAN_NB partials (was single-thread)
__global__ void k_scan_part() {
    __shared__ int s[256];
    int t = threadIdx.x;
    int v = (t < SCAN_NB) ? g_part[t] : 0;
    s[t] = v;
    __syncthreads();
    for (int off = 1; off < 256; off <<= 1) {
        int u = (t >= off) ? s[t - off] : 0;
        __syncthreads();
        s[t] += u;
        __syncthreads();
    }
    if (t < SCAN_NB) g_part[t] = s[t] - v;  // exclusive
}

__global__ void k_scan_add() {
    int i = blockIdx.x * blockDim.x + threadIdx.x;
    if (i < N_NODES) {
        int r = g_rowptr[i] + g_part[i / SCAN_B];
        g_rowptr[i] = r;
        g_fill[i] = r;
    }
    if (i == 0) g_rowptr[N_NODES] = N_EDGES;
}

__global__ void k_scatter(const void* ei) {
    int e = blockIdx.x * blockDim.x + threadIdx.x;
    if (e < N_EDGES) {
        int d = edst(ei, e);
        int p = atomicAdd(&g_fill[d], 1);
        g_col[p] = esrc(ei, e);
    }
}

// ---------------- mean aggregation of x: one warp per node ----------------
__global__ void k_agg1(const float* __restrict__ x) {
    int warp = (blockIdx.x * blockDim.x + threadIdx.x) >> 5;
    int lane = threadIdx.x & 31;
    if (warp >= N_NODES) return;
    float a0 = 0.f, a1 = 0.f;
    int s0 = g_rowptr[warp], s1 = g_rowptr[warp + 1];
    for (int e = s0; e < s1; e++) {
        const float* f = x + (size_t)g_col[e] * DIN;
        a0 += f[lane];
        a1 += f[lane + 32];
    }
    float inv = 1.f / (float)max(s1 - s0, 1);
    g_agg1[(size_t)warp * DIN + lane] = a0 * inv;
    g_agg1[(size_t)warp * DIN + lane + 32] = a1 * inv;
}

// ---------------- layer 1: h1 = relu([agg1|x] @ [W1l|W1r]^T + b1) ----------
// Block tile: 128 outputs x 32 nodes. Each warp: 4 nodes, each lane: 4 outputs
// (o = lane + 32j). Per k4-step: 8 LDS.128 (32 crossbar cyc) vs 64 FFMA
// (32 SM-cyc) -> FFMA-bound (was LDS-bound 2.5x with O=2,ND=3).
#define L1_WPAD 132
#define L1_NT 32              // nodes per tile
#define L1_ITER 4
#define L1_NPB (L1_NT * L1_ITER)  // 128 nodes/block
#define L1_SMEM ((DHID * L1_WPAD + L1_NT * DHID) * 4)

__global__ void __launch_bounds__(256) k_lin1(const float* __restrict__ x,
                                              const float* __restrict__ W1l,
                                              const float* __restrict__ W1r,
                                              const float* __restrict__ b1) {
    extern __shared__ float sm[];
    float* sW = sm;                    // [128][132]
    float* sIn = sm + DHID * L1_WPAD;  // [32][128]
    int tid = threadIdx.x;

    // stage combined weight [128 out][128 k] = [W1l | W1r], o-major, pad 132
    for (int idx = tid; idx < DHID * DHID; idx += 256) {
        int o = idx >> 7, k = idx & 127;
        sW[o * L1_WPAD + k] = (k < DIN) ? W1l[o * DIN + k] : W1r[o * DIN + (k - DIN)];
    }
    __syncthreads();

    int w = tid >> 5, lane = tid & 31;
    float bb[4];
#pragma unroll
    for (int j = 0; j < 4; j++) bb[j] = b1[lane + 32 * j];

    for (int it = 0; it < L1_ITER; it++) {
        int base = blockIdx.x * L1_NPB + it * L1_NT;
        // stage input tile [32 nodes][128] = [agg1 | x]
        {
            int nl = tid >> 3, q = tid & 7;  // thread loads 16 floats of one node
            int n = base + nl;
#pragma unroll
            for (int c = 0; c < 4; c++) {
                int k = q * 16 + c * 4;
                float4 v = make_float4(0.f, 0.f, 0.f, 0.f);
                if (n < N_NODES) {
                    v = (k < DIN)
                            ? *(const float4*)&g_agg1[(size_t)n * DIN + k]
                            : *(const float4*)&x[(size_t)n * DIN + (k - DIN)];
                }
                *(float4*)&sIn[nl * DHID + k] = v;
            }
        }
        __syncthreads();

        float acc[4][4];
#pragma unroll
        for (int nd = 0; nd < 4; nd++)
#pragma unroll
            for (int j = 0; j < 4; j++) acc[nd][j] = bb[j];

        const float* inB = sIn + (w * 4) * DHID;
#pragma unroll 4
        for (int k = 0; k < DHID; k += 4) {
            float4 wv[4];
#pragma unroll
            for (int j = 0; j < 4; j++)
                wv[j] = *(const float4*)&sW[(lane + 32 * j) * L1_WPAD + k];
#pragma unroll
            for (int nd = 0; nd < 4; nd++) {
                float4 iv = *(const float4*)&inB[nd * DHID + k];
#pragma unroll
                for (int j = 0; j < 4; j++) {
                    acc[nd][j] = fmaf(wv[j].x, iv.x, acc[nd][j]);
                    acc[nd][j] = fmaf(wv[j].y, iv.y, acc[nd][j]);
                    acc[nd][j] = fmaf(wv[j].z, iv.z, acc[nd][j]);
                    acc[nd][j] = fmaf(wv[j].w, iv.w, acc[nd][j]);
                }
            }
        }
#pragma unroll
        for (int nd = 0; nd < 4; nd++) {
            int n = base + w * 4 + nd;
            if (n < N_NODES) {
#pragma unroll
                for (int j = 0; j < 4; j++) {
                    float r = acc[nd][j];
                    g_h1[(size_t)n * DHID + lane + 32 * j] = r > 0.f ? r : 0.f;
                }
            }
        }
        __syncthreads();
    }
}

// ---------------- layer 2 GEMMs (transform BEFORE aggregate) --------------
// y2l = h1 @ W2l^T, y2r = h1 @ W2r^T : combined 80 outputs x K=128.
// Lane outputs o = lane + 32j, j<3 (o<80 valid). 83% lane efficiency.
#define L2_WPAD 132
#define L2_OUT 80
#define L2_NT 32
#define L2_ITER 4
#define L2_NPB (L2_NT * L2_ITER)
#define L2_SMEM ((L2_OUT * L2_WPAD + L2_NT * DHID) * 4)

__global__ void __launch_bounds__(256) k_gemm2(const float* __restrict__ W2l,
                                               const float* __restrict__ W2r) {
    extern __shared__ float sm[];
    float* sW = sm;                      // [80][132]
    float* sIn = sm + L2_OUT * L2_WPAD;  // [32][128]
    int tid = threadIdx.x;

    for (int idx = tid; idx < L2_OUT * DHID; idx += 256) {
        int o = idx >> 7, k = idx & 127;
        sW[o * L2_WPAD + k] =
            (o < DOUT) ? W2l[o * DHID + k] : W2r[(o - DOUT) * DHID + k];
    }
    __syncthreads();

    int w = tid >> 5, lane = tid & 31;

    for (int it = 0; it < L2_ITER; it++) {
        int base = blockIdx.x * L2_NPB + it * L2_NT;
        {
            int nl = tid >> 3, q = tid & 7;
            int n = base + nl;
#pragma unroll
            for (int c = 0; c < 4; c++) {
                int k = q * 16 + c * 4;
                float4 v = make_float4(0.f, 0.f, 0.f, 0.f);
                if (n < N_NODES) v = *(const float4*)&g_h1[(size_t)n * DHID + k];
                *(float4*)&sIn[nl * DHID + k] = v;
            }
        }
        __syncthreads();

        float acc[4][3];
#pragma unroll
        for (int nd = 0; nd < 4; nd++)
#pragma unroll
            for (int j = 0; j < 3; j++) acc[nd][j] = 0.f;

        const float* inB = sIn + (w * 4) * DHID;
#pragma unroll 4
        for (int k = 0; k < DHID; k += 4) {
            float4 wv[3];
            wv[0] = *(const float4*)&sW[lane * L2_WPAD + k];
            wv[1] = *(const float4*)&sW[(lane + 32) * L2_WPAD + k];
            wv[2] = (lane < 16)
                        ? *(const float4*)&sW[(lane + 64) * L2_WPAD + k]
                        : make_float4(0.f, 0.f, 0.f, 0.f);
#pragma unroll
            for (int nd = 0; nd < 4; nd++) {
                float4 iv = *(const float4*)&inB[nd * DHID + k];
#pragma unroll
                for (int j = 0; j < 3; j++) {
                    acc[nd][j] = fmaf(wv[j].x, iv.x, acc[nd][j]);
                    acc[nd][j] = fmaf(wv[j].y, iv.y, acc[nd][j]);
                    acc[nd][j] = fmaf(wv[j].z, iv.z, acc[nd][j]);
                    acc[nd][j] = fmaf(wv[j].w, iv.w, acc[nd][j]);
                }
            }
        }
#pragma unroll
        for (int nd = 0; nd < 4; nd++) {
            int n = base + w * 4 + nd;
            if (n < N_NODES) {
#pragma unroll
                for (int j = 0; j < 3; j++) {
                    int o = lane + 32 * j;
                    if (o < DOUT)
                        g_y2l[(size_t)n * DOUT + o] = acc[nd][j];
                    else if (o < L2_OUT)
                        g_y2r[(size_t)n * DOUT + (o - DOUT)] = acc[nd][j];
                }
            }
        }
        __syncthreads();
    }
}

// ---------------- final: out = log_softmax(mean-agg(y2l) + b2 + y2r) -------
// One warp per node; 160 B/edge gather (was 512 B before the restructure).
__global__ void k_out(const float* __restrict__ b2, float* __restrict__ out) {
    int warp = (blockIdx.x * blockDim.x + threadIdx.x) >> 5;
    int lane = threadIdx.x & 31;
    if (warp >= N_NODES) return;
    float a0 = 0.f, a1 = 0.f;
    int s0 = g_rowptr[warp], s1 = g_rowptr[warp + 1];
    for (int e = s0; e < s1; e++) {
        const float* f = g_y2l + (size_t)g_col[e] * DOUT;
        a0 += f[lane];
        if (lane < 8) a1 += f[32 + lane];
    }
    float inv = 1.f / (float)max(s1 - s0, 1);
    size_t nb = (size_t)warp * DOUT;
    float v0 = a0 * inv + b2[lane] + g_y2r[nb + lane];
    float v1 = (lane < 8) ? (a1 * inv + b2[32 + lane] + g_y2r[nb + 32 + lane])
                          : -INFINITY;
    float m = fmaxf(v0, v1);
    for (int off = 16; off; off >>= 1)
        m = fmaxf(m, __shfl_xor_sync(0xffffffffu, m, off));
    float s = expf(v0 - m) + ((lane < 8) ? expf(v1 - m) : 0.f);
    for (int off = 16; off; off >>= 1)
        s += __shfl_xor_sync(0xffffffffu, s, off);
    float lse = m + logf(s);
    out[nb + lane] = v0 - lse;
    if (lane < 8) out[nb + 32 + lane] = v1 - lse;
}

// ---------------- launch --------------------------------------------------
extern "C" void kernel_launch(void* const* d_in, const int* in_sizes, int n_in,
                              void* d_out, int out_size) {
    const float* x = (const float*)d_in[0];
    const void* ei = d_in[1];
    const float* W1l = (const float*)d_in[2];
    const float* b1 = (const float*)d_in[3];
    const float* W1r = (const float*)d_in[4];
    const float* W2l = (const float*)d_in[5];
    const float* b2 = (const float*)d_in[6];
    const float* W2r = (const float*)d_in[7];
    float* out = (float*)d_out;

    cudaFuncSetAttribute(k_lin1, cudaFuncAttributeMaxDynamicSharedMemorySize,
                         L1_SMEM);
    cudaFuncSetAttribute(k_gemm2, cudaFuncAttributeMaxDynamicSharedMemorySize,
                         L2_SMEM);

    k_detect<<<1, 256>>>((const int*)ei);
    k_init_deg<<<(N_NODES + 255) / 256, 256>>>();
    k_hist<<<(N_EDGES + 255) / 256, 256>>>(ei);
    k_scan_block<<<SCAN_NB, SCAN_B>>>();
    k_scan_part<<<1, 256>>>();
    k_scan_add<<<(N_NODES + 255) / 256, 256>>>();
    k_scatter<<<(N_EDGES + 255) / 256, 256>>>(ei);

    // layer 1
    k_agg1<<<(N_NODES * 32 + 255) / 256, 256>>>(x);
    k_lin1<<<(N_NODES + L1_NPB - 1) / L1_NPB, 256, L1_SMEM>>>(x, W1l, W1r, b1);

    // layer 2 (transform-then-aggregate) + fused softmax
    k_gemm2<<<(N_NODES + L2_NPB - 1) / L2_NPB, 256, L2_SMEM>>>(W2l, W2r);
    k_out<<<(N_NODES * 32 + 255) / 256, 256>>>(b2, out);
}

// round 4
// speedup vs baseline: 2.3944x; 1.2128x over previous
#include <cuda_runtime.h>
#include <cuda_bf16.h>
#include <math.h>
#include <stdint.h>

#define N_NODES 100000
#define N_EDGES 1600000
#define DIN 64
#define DHID 128
#define DOUT 40
#define SCAN_B 512
#define SCAN_NB ((N_NODES + SCAN_B - 1) / SCAN_B)
#define TILE_M 128
#define N_TILES ((N_NODES + TILE_M - 1) / TILE_M)  // 782
#define W2ROWS 80
#define LDS_ROW 136  // bf16 elems per SMEM row (128 + 8 pad), 272 B

// ---------------- device scratch ----------------
__device__ int g_is64;
__device__ int g_deg[N_NODES];
__device__ int g_rowptr[N_NODES + 1];
__device__ int g_fill[N_NODES];
__device__ int g_col[N_EDGES];
__device__ int g_part[256];
// bf16 hi/lo pairs packed 2-per-uint32, row-major [node][64 pairs] (=128 cols)
__device__ uint32_t g_inh[(size_t)N_NODES * 64];
__device__ uint32_t g_inl[(size_t)N_NODES * 64];
__device__ uint32_t g_h1h[(size_t)N_NODES * 64];
__device__ uint32_t g_h1l[(size_t)N_NODES * 64];
__device__ uint32_t g_w1h[DHID * 64], g_w1l[DHID * 64];      // [128 out][128 k]
__device__ uint32_t g_w2h[W2ROWS * 64], g_w2l[W2ROWS * 64];  // [80 out][128 k]
__device__ float g_y2l[(size_t)N_NODES * DOUT];
__device__ float g_y2r[(size_t)N_NODES * DOUT];

// ---------------- helpers ----------------
__device__ __forceinline__ void mma16816(float* c, const uint32_t* a,
                                         uint32_t b0, uint32_t b1) {
    asm volatile(
        "mma.sync.aligned.m16n8k16.row.col.f32.bf16.bf16.f32 "
        "{%0,%1,%2,%3}, {%4,%5,%6,%7}, {%8,%9}, {%0,%1,%2,%3};"
        : "+f"(c[0]), "+f"(c[1]), "+f"(c[2]), "+f"(c[3])
        : "r"(a[0]), "r"(a[1]), "r"(a[2]), "r"(a[3]), "r"(b0), "r"(b1));
}
__device__ __forceinline__ void split_bf16(float v, __nv_bfloat16& h, float& lo) {
    h = __float2bfloat16_rn(v);
    lo = v - __bfloat162float(h);
}
__device__ __forceinline__ uint32_t pack_split_hi(float v0, float v1) {
    __nv_bfloat162 p = __nv_bfloat162(__float2bfloat16_rn(v0), __float2bfloat16_rn(v1));
    return *(uint32_t*)&p;
}
// copy [rows][64 uint32] global -> SMEM bf16 rows of stride LDS_ROW
__device__ __forceinline__ void ld_tile(__nv_bfloat16* s, const uint32_t* g,
                                        int base, int rows, int maxn) {
    for (int i = threadIdx.x; i < rows * 16; i += 256) {
        int r = i >> 4, c8 = i & 15;
        int n = base + r;
        uint4 v = make_uint4(0, 0, 0, 0);
        if (n < maxn) v = *(const uint4*)(g + (size_t)n * 64 + c8 * 4);
        *(uint4*)((char*)s + r * (LDS_ROW * 2) + c8 * 16) = v;
    }
}

// ---------------- edge index access (int64 or int32, runtime-detected) ----
__device__ __forceinline__ int esrc(const void* ei, int e) {
    return g_is64 ? (int)((const long long*)ei)[e] : ((const int*)ei)[e];
}
__device__ __forceinline__ int edst(const void* ei, int e) {
    return g_is64 ? (int)((const long long*)ei)[(size_t)N_EDGES + e]
                  : ((const int*)ei)[(size_t)N_EDGES + e];
}

__global__ void k_detect(const int* ei) {
    bool ok = true;
    for (int i = threadIdx.x; i < 4096; i += blockDim.x)
        if (ei[2 * i + 1] != 0) ok = false;
    int all = __syncthreads_and((int)ok);
    if (threadIdx.x == 0) g_is64 = all ? 1 : 0;
}
__global__ void k_init_deg() {
    int i = blockIdx.x * blockDim.x + threadIdx.x;
    if (i < N_NODES) g_deg[i] = 0;
}
__global__ void k_hist(const void* ei) {
    int e = blockIdx.x * blockDim.x + threadIdx.x;
    if (e < N_EDGES) atomicAdd(&g_deg[edst(ei, e)], 1);
}
__global__ void k_scan_block() {
    __shared__ int s[SCAN_B];
    int i = blockIdx.x * SCAN_B + threadIdx.x;
    int v = (i < N_NODES) ? g_deg[i] : 0;
    s[threadIdx.x] = v;
    __syncthreads();
    for (int off = 1; off < SCAN_B; off <<= 1) {
        int t = (threadIdx.x >= off) ? s[threadIdx.x - off] : 0;
        __syncthreads();
        s[threadIdx.x] += t;
        __syncthreads();
    }
    if (i < N_NODES) g_rowptr[i] = s[threadIdx.x] - v;
    if (threadIdx.x == SCAN_B - 1) g_part[blockIdx.x] = s[SCAN_B - 1];
}
__global__ void k_scan_part() {
    __shared__ int s[256];
    int t = threadIdx.x;
    int v = (t < SCAN_NB) ? g_part[t] : 0;
    s[t] = v;
    __syncthreads();
    for (int off = 1; off < 256; off <<= 1) {
        int u = (t >= off) ? s[t - off] : 0;
        __syncthreads();
        s[t] += u;
        __syncthreads();
    }
    if (t < SCAN_NB) g_part[t] = s[t] - v;
}
__global__ void k_scan_add() {
    int i = blockIdx.x * blockDim.x + threadIdx.x;
    if (i < N_NODES) {
        int r = g_rowptr[i] + g_part[i / SCAN_B];
        g_rowptr[i] = r;
        g_fill[i] = r;
    }
    if (i == 0) g_rowptr[N_NODES] = N_EDGES;
}
__global__ void k_scatter(const void* ei) {
    int e = blockIdx.x * blockDim.x + threadIdx.x;
    if (e < N_EDGES) {
        int d = edst(ei, e);
        int p = atomicAdd(&g_fill[d], 1);
        g_col[p] = esrc(ei, e);
    }
}

// ---------------- agg of x -> bf16 cols 0..63 of g_inh/g_inl -------------
__global__ void k_agg1(const float* __restrict__ x) {
    int warp = (blockIdx.x * blockDim.x + threadIdx.x) >> 5;
    int lane = threadIdx.x & 31;
    if (warp >= N_NODES) return;
    float a0 = 0.f, a1 = 0.f;
    int s0 = g_rowptr[warp], s1 = g_rowptr[warp + 1];
    for (int e = s0; e < s1; e++) {
        const float* f = x + (size_t)g_col[e] * DIN;
        a0 += f[lane];
        a1 += f[lane + 32];
    }
    float inv = 1.f / (float)max(s1 - s0, 1);
    a0 *= inv; a1 *= inv;
    __nv_bfloat16* ph = (__nv_bfloat16*)g_inh;
    __nv_bfloat16* pl = (__nv_bfloat16*)g_inl;
    size_t b = (size_t)warp * DHID;
    __nv_bfloat16 h; float lo;
    split_bf16(a0, h, lo);
    ph[b + lane] = h; pl[b + lane] = __float2bfloat16_rn(lo);
    split_bf16(a1, h, lo);
    ph[b + lane + 32] = h; pl[b + lane + 32] = __float2bfloat16_rn(lo);
}

// ---------------- x -> bf16 cols 64..127 of g_inh/g_inl ----------------
__global__ void k_conv_x(const float* __restrict__ x) {
    int idx = blockIdx.x * blockDim.x + threadIdx.x;
    if (idx >= N_NODES * 32) return;
    int n = idx >> 5, q = idx & 31;
    float2 v = *(const float2*)&x[(size_t)n * DIN + 2 * q];
    __nv_bfloat16 h0, h1; float l0, l1;
    split_bf16(v.x, h0, l0);
    split_bf16(v.y, h1, l1);
    __nv_bfloat162 ph = __nv_bfloat162(h0, h1);
    __nv_bfloat162 pl = __floats2bfloat162_rn(l0, l1);
    g_inh[(size_t)n * 64 + 32 + q] = *(uint32_t*)&ph;
    g_inl[(size_t)n * 64 + 32 + q] = *(uint32_t*)&pl;
}

// ---------------- weight conversion (both layers) ----------------
__global__ void k_conv_w(const float* __restrict__ W1l, const float* __restrict__ W1r,
                         const float* __restrict__ W2l, const float* __restrict__ W2r) {
    int idx = blockIdx.x * blockDim.x + threadIdx.x;
    int tot1 = DHID * 64;
    if (idx < tot1) {
        int o = idx >> 6, q = idx & 63;
        int c = 2 * q;
        float v0 = (c < 64) ? W1l[o * 64 + c] : W1r[o * 64 + c - 64];
        float v1 = (c < 64) ? W1l[o * 64 + c + 1] : W1r[o * 64 + c - 63];
        __nv_bfloat16 h0, h1; float l0, l1;
        split_bf16(v0, h0, l0); split_bf16(v1, h1, l1);
        __nv_bfloat162 ph = __nv_bfloat162(h0, h1);
        __nv_bfloat162 pl = __floats2bfloat162_rn(l0, l1);
        g_w1h[idx] = *(uint32_t*)&ph;
        g_w1l[idx] = *(uint32_t*)&pl;
    } else if (idx < tot1 + W2ROWS * 64) {
        int j = idx - tot1;
        int o = j >> 6, q = j & 63;
        int c = 2 * q;
        float v0 = (o < DOUT) ? W2l[o * DHID + c] : W2r[(o - DOUT) * DHID + c];
        float v1 = (o < DOUT) ? W2l[o * DHID + c + 1] : W2r[(o - DOUT) * DHID + c + 1];
        __nv_bfloat16 h0, h1; float l0, l1;
        split_bf16(v0, h0, l0); split_bf16(v1, h1, l1);
        __nv_bfloat162 ph = __nv_bfloat162(h0, h1);
        __nv_bfloat162 pl = __floats2bfloat162_rn(l0, l1);
        g_w2h[j] = *(uint32_t*)&ph;
        g_w2l[j] = *(uint32_t*)&pl;
    }
}

// ---------------- mma.sync layer 1: h1 = relu([agg|x]@[W1l|W1r]^T + b1) ---
// split-2 bf16 (3 products), warp tile 32x64, CTA tile 128x128, K=128.
#define L1_SMEM (4 * 128 * LDS_ROW * 2 + 512)
__global__ void __launch_bounds__(256) k_mma1(const float* __restrict__ b1) {
    extern __shared__ char dsm[];
    __nv_bfloat16* sAh = (__nv_bfloat16*)dsm;
    __nv_bfloat16* sAl = (__nv_bfloat16*)(dsm + 128 * LDS_ROW * 2);
    __nv_bfloat16* sWh = (__nv_bfloat16*)(dsm + 2 * 128 * LDS_ROW * 2);
    __nv_bfloat16* sWl = (__nv_bfloat16*)(dsm + 3 * 128 * LDS_ROW * 2);
    float* sB = (float*)(dsm + 4 * 128 * LDS_ROW * 2);
    int tid = threadIdx.x;
    int base = blockIdx.x * TILE_M;

    ld_tile(sAh, g_inh, base, 128, N_NODES);
    ld_tile(sAl, g_inl, base, 128, N_NODES);
    ld_tile(sWh, g_w1h, 0, 128, 1 << 30);
    ld_tile(sWl, g_w1l, 0, 128, 1 << 30);
    if (tid < DHID) sB[tid] = b1[tid];
    __syncthreads();

    int wid = tid >> 5, lane = tid & 31;
    int Rb = (wid & 3) * 32;   // warp M offset
    int Nb = (wid >> 2) * 64;  // warp N offset
    int qr = lane >> 2;        // 0..7
    int qc = 2 * (lane & 3);   // 0,2,4,6

    float acc[2][8][4];
#pragma unroll
    for (int mt = 0; mt < 2; mt++)
#pragma unroll
        for (int nt = 0; nt < 8; nt++)
#pragma unroll
            for (int j = 0; j < 4; j++) acc[mt][nt][j] = 0.f;

    for (int ks = 0; ks < 8; ks++) {
        int kc = ks * 16 + qc;
        uint32_t ah[2][4], al[2][4];
#pragma unroll
        for (int mt = 0; mt < 2; mt++) {
            int r = Rb + mt * 16 + qr;
            ah[mt][0] = *(const uint32_t*)(sAh + r * LDS_ROW + kc);
            ah[mt][1] = *(const uint32_t*)(sAh + (r + 8) * LDS_ROW + kc);
            ah[mt][2] = *(const uint32_t*)(sAh + r * LDS_ROW + kc + 8);
            ah[mt][3] = *(const uint32_t*)(sAh + (r + 8) * LDS_ROW + kc + 8);
            al[mt][0] = *(const uint32_t*)(sAl + r * LDS_ROW + kc);
            al[mt][1] = *(const uint32_t*)(sAl + (r + 8) * LDS_ROW + kc);
            al[mt][2] = *(const uint32_t*)(sAl + r * LDS_ROW + kc + 8);
            al[mt][3] = *(const uint32_t*)(sAl + (r + 8) * LDS_ROW + kc + 8);
        }
#pragma unroll
        for (int nt = 0; nt < 8; nt++) {
            int n = Nb + nt * 8 + qr;
            uint32_t bh0 = *(const uint32_t*)(sWh + n * LDS_ROW + kc);
            uint32_t bh1 = *(const uint32_t*)(sWh + n * LDS_ROW + kc + 8);
            uint32_t bl0 = *(const uint32_t*)(sWl + n * LDS_ROW + kc);
            uint32_t bl1 = *(const uint32_t*)(sWl + n * LDS_ROW + kc + 8);
#pragma unroll
            for (int mt = 0; mt < 2; mt++) {
                mma16816(acc[mt][nt], ah[mt], bh0, bh1);
                mma16816(acc[mt][nt], al[mt], bh0, bh1);
                mma16816(acc[mt][nt], ah[mt], bl0, bl1);
            }
        }
    }

    // epilogue: bias + relu + bf16 resplit -> g_h1h/g_h1l
#pragma unroll
    for (int mt = 0; mt < 2; mt++) {
#pragma unroll
        for (int nt = 0; nt < 8; nt++) {
            int c = Nb + nt * 8 + qc;
            int cp = c >> 1;
            float bv0 = sB[c], bv1 = sB[c + 1];
            int n0 = base + Rb + mt * 16 + qr;
            float v0 = acc[mt][nt][0] + bv0, v1 = acc[mt][nt][1] + bv1;
            float v2 = acc[mt][nt][2] + bv0, v3 = acc[mt][nt][3] + bv1;
            v0 = v0 > 0.f ? v0 : 0.f;
            v1 = v1 > 0.f ? v1 : 0.f;
            v2 = v2 > 0.f ? v2 : 0.f;
            v3 = v3 > 0.f ? v3 : 0.f;
            if (n0 < N_NODES) {
                uint32_t hp = pack_split_hi(v0, v1);
                __nv_bfloat162 hb = *(__nv_bfloat162*)&hp;
                float l0 = v0 - __bfloat162float(hb.x);
                float l1 = v1 - __bfloat162float(hb.y);
                __nv_bfloat162 lp = __floats2bfloat162_rn(l0, l1);
                g_h1h[(size_t)n0 * 64 + cp] = hp;
                g_h1l[(size_t)n0 * 64 + cp] = *(uint32_t*)&lp;
            }
            int n1 = n0 + 8;
            if (n1 < N_NODES) {
                uint32_t hp = pack_split_hi(v2, v3);
                __nv_bfloat162 hb = *(__nv_bfloat162*)&hp;
                float l0 = v2 - __bfloat162float(hb.x);
                float l1 = v3 - __bfloat162float(hb.y);
                __nv_bfloat162 lp = __floats2bfloat162_rn(l0, l1);
                g_h1h[(size_t)n1 * 64 + cp] = hp;
                g_h1l[(size_t)n1 * 64 + cp] = *(uint32_t*)&lp;
            }
        }
    }
}

// ---------------- mma.sync layer 2: [y2l|y2r] = h1 @ [W2l;W2r]^T ----------
// CTA tile 128x80, warp tile 32x40.
#define L2_SMEM (2 * 128 * LDS_ROW * 2 + 2 * W2ROWS * LDS_ROW * 2)
__global__ void __launch_bounds__(256) k_mma2() {
    extern __shared__ char dsm[];
    __nv_bfloat16* sAh = (__nv_bfloat16*)dsm;
    __nv_bfloat16* sAl = (__nv_bfloat16*)(dsm + 128 * LDS_ROW * 2);
    __nv_bfloat16* sWh = (__nv_bfloat16*)(dsm + 2 * 128 * LDS_ROW * 2);
    __nv_bfloat16* sWl = (__nv_bfloat16*)(dsm + 2 * 128 * LDS_ROW * 2 + W2ROWS * LDS_ROW * 2);
    int tid = threadIdx.x;
    int base = blockIdx.x * TILE_M;

    ld_tile(sAh, g_h1h, base, 128, N_NODES);
    ld_tile(sAl, g_h1l, base, 128, N_NODES);
    ld_tile(sWh, g_w2h, 0, W2ROWS, 1 << 30);
    ld_tile(sWl, g_w2l, 0, W2ROWS, 1 << 30);
    __syncthreads();

    int wid = tid >> 5, lane = tid & 31;
    int Rb = (wid & 3) * 32;
    int Nb = (wid >> 2) * 40;
    int qr = lane >> 2;
    int qc = 2 * (lane & 3);

    float acc[2][5][4];
#pragma unroll
    for (int mt = 0; mt < 2; mt++)
#pragma unroll
        for (int nt = 0; nt < 5; nt++)
#pragma unroll
            for (int j = 0; j < 4; j++) acc[mt][nt][j] = 0.f;

    for (int ks = 0; ks < 8; ks++) {
        int kc = ks * 16 + qc;
        uint32_t ah[2][4], al[2][4];
#pragma unroll
        for (int mt = 0; mt < 2; mt++) {
            int r = Rb + mt * 16 + qr;
            ah[mt][0] = *(const uint32_t*)(sAh + r * LDS_ROW + kc);
            ah[mt][1] = *(const uint32_t*)(sAh + (r + 8) * LDS_ROW + kc);
            ah[mt][2] = *(const uint32_t*)(sAh + r * LDS_ROW + kc + 8);
            ah[mt][3] = *(const uint32_t*)(sAh + (r + 8) * LDS_ROW + kc + 8);
            al[mt][0] = *(const uint32_t*)(sAl + r * LDS_ROW + kc);
            al[mt][1] = *(const uint32_t*)(sAl + (r + 8) * LDS_ROW + kc);
            al[mt][2] = *(const uint32_t*)(sAl + r * LDS_ROW + kc + 8);
            al[mt][3] = *(const uint32_t*)(sAl + (r + 8) * LDS_ROW + kc + 8);
        }
#pragma unroll
        for (int nt = 0; nt < 5; nt++) {
            int n = Nb + nt * 8 + qr;
            uint32_t bh0 = *(const uint32_t*)(sWh + n * LDS_ROW + kc);
            uint32_t bh1 = *(const uint32_t*)(sWh + n * LDS_ROW + kc + 8);
            uint32_t bl0 = *(const uint32_t*)(sWl + n * LDS_ROW + kc);
            uint32_t bl1 = *(const uint32_t*)(sWl + n * LDS_ROW + kc + 8);
#pragma unroll
            for (int mt = 0; mt < 2; mt++) {
                mma16816(acc[mt][nt], ah[mt], bh0, bh1);
                mma16816(acc[mt][nt], al[mt], bh0, bh1);
                mma16816(acc[mt][nt], ah[mt], bl0, bl1);
            }
        }
    }

#pragma unroll
    for (int mt = 0; mt < 2; mt++) {
#pragma unroll
        for (int nt = 0; nt < 5; nt++) {
            int c = Nb + nt * 8 + qc;  // 0..78 even
            float* dst = (c < DOUT) ? g_y2l : g_y2r;
            int cc = (c < DOUT) ? c : c - DOUT;
            int n0 = base + Rb + mt * 16 + qr;
            if (n0 < N_NODES)
                *(float2*)&dst[(size_t)n0 * DOUT + cc] =
                    make_float2(acc[mt][nt][0], acc[mt][nt][1]);
            int n1 = n0 + 8;
            if (n1 < N_NODES)
                *(float2*)&dst[(size_t)n1 * DOUT + cc] =
                    make_float2(acc[mt][nt][2], acc[mt][nt][3]);
        }
    }
}

// ---------------- final: out = log_softmax(mean-agg(y2l) + b2 + y2r) ------
__global__ void k_out(const float* __restrict__ b2, float* __restrict__ out) {
    int warp = (blockIdx.x * blockDim.x + threadIdx.x) >> 5;
    int lane = threadIdx.x & 31;
    if (warp >= N_NODES) return;
    float a0 = 0.f, a1 = 0.f;
    int s0 = g_rowptr[warp], s1 = g_rowptr[warp + 1];
    for (int e = s0; e < s1; e++) {
        const float* f = g_y2l + (size_t)g_col[e] * DOUT;
        a0 += f[lane];
        if (lane < 8) a1 += f[32 + lane];
    }
    float inv = 1.f / (float)max(s1 - s0, 1);
    size_t nb = (size_t)warp * DOUT;
    float v0 = a0 * inv + b2[lane] + g_y2r[nb + lane];
    float v1 = (lane < 8) ? (a1 * inv + b2[32 + lane] + g_y2r[nb + 32 + lane])
                          : -INFINITY;
    float m = fmaxf(v0, v1);
    for (int off = 16; off; off >>= 1)
        m = fmaxf(m, __shfl_xor_sync(0xffffffffu, m, off));
    float s = expf(v0 - m) + ((lane < 8) ? expf(v1 - m) : 0.f);
    for (int off = 16; off; off >>= 1)
        s += __shfl_xor_sync(0xffffffffu, s, off);
    float lse = m + logf(s);
    out[nb + lane] = v0 - lse;
    if (lane < 8) out[nb + 32 + lane] = v1 - lse;
}

// ---------------- launch --------------------------------------------------
extern "C" void kernel_launch(void* const* d_in, const int* in_sizes, int n_in,
                              void* d_out, int out_size) {
    const float* x = (const float*)d_in[0];
    const void* ei = d_in[1];
    const float* W1l = (const float*)d_in[2];
    const float* b1 = (const float*)d_in[3];
    const float* W1r = (const float*)d_in[4];
    const float* W2l = (const float*)d_in[5];
    const float* b2 = (const float*)d_in[6];
    const float* W2r = (const float*)d_in[7];
    float* out = (float*)d_out;

    cudaFuncSetAttribute(k_mma1, cudaFuncAttributeMaxDynamicSharedMemorySize, L1_SMEM);
    cudaFuncSetAttribute(k_mma2, cudaFuncAttributeMaxDynamicSharedMemorySize, L2_SMEM);

    k_detect<<<1, 256>>>((const int*)ei);
    k_init_deg<<<(N_NODES + 255) / 256, 256>>>();
    k_hist<<<(N_EDGES + 255) / 256, 256>>>(ei);
    k_scan_block<<<SCAN_NB, SCAN_B>>>();
    k_scan_part<<<1, 256>>>();
    k_scan_add<<<(N_NODES + 255) / 256, 256>>>();
    k_scatter<<<(N_EDGES + 255) / 256, 256>>>(ei);

    // conversions (independent of CSR)
    k_conv_x<<<(N_NODES * 32 + 255) / 256, 256>>>(x);
    k_conv_w<<<((DHID * 64 + W2ROWS * 64) + 255) / 256, 256>>>(W1l, W1r, W2l, W2r);

    // layer 1
    k_agg1<<<(N_NODES * 32 + 255) / 256, 256>>>(x);
    k_mma1<<<N_TILES, 256, L1_SMEM>>>(b1);

    // layer 2 (transform-then-aggregate) + fused softmax
    k_mma2<<<N_TILES, 256, L2_SMEM>>>();
    k_out<<<(N_NODES * 32 + 255) / 256, 256>>>(b2, out);
}

// round 5
// speedup vs baseline: 2.9364x; 1.2264x over previous
#include <cuda_runtime.h>
#include <cuda_bf16.h>
#include <math.h>
#include <stdint.h>

#define N_NODES 100000
#define N_EDGES 1600000
#define DIN 64
#define DHID 128
#define DOUT 40
#define SCAN_B 512
#define SCAN_NB ((N_NODES + SCAN_B - 1) / SCAN_B)
#define TILE_M 128
#define N_TILES ((N_NODES + TILE_M - 1) / TILE_M)  // 782
#define W2ROWS 80
#define LDS_ROW 136  // bf16 elems per SMEM row (128 + 8 pad) -> conflict-free frags

// SMEM byte offsets for fused kernel
#define SM_AH 0
#define SM_AL 34816
#define SM_W1H 69632
#define SM_W1L 104448
#define SM_W2H 139264
#define SM_W2L 161024
#define SM_BIAS 182784
#define SM_TOTAL 183424

// ---------------- device scratch ----------------
__device__ int g_is64;
__device__ int g_deg[N_NODES];
__device__ int g_rowptr[N_NODES + 1];
__device__ int g_fill[N_NODES];
__device__ int g_col[N_EDGES];
__device__ int g_part[256];
__device__ uint32_t g_w1h[DHID * 64], g_w1l[DHID * 64];      // [128 out][128 k] bf16x2
__device__ uint32_t g_w2h[W2ROWS * 64], g_w2l[W2ROWS * 64];  // [80 out][128 k]
__device__ float g_y2l[(size_t)N_NODES * DOUT];
__device__ float g_y2r[(size_t)N_NODES * DOUT];

// ---------------- helpers ----------------
__device__ __forceinline__ void mma16816(float* c, const uint32_t* a,
                                         uint32_t b0, uint32_t b1) {
    asm volatile(
        "mma.sync.aligned.m16n8k16.row.col.f32.bf16.bf16.f32 "
        "{%0,%1,%2,%3}, {%4,%5,%6,%7}, {%8,%9}, {%0,%1,%2,%3};"
        : "+f"(c[0]), "+f"(c[1]), "+f"(c[2]), "+f"(c[3])
        : "r"(a[0]), "r"(a[1]), "r"(a[2]), "r"(a[3]), "r"(b0), "r"(b1));
}
__device__ __forceinline__ void split_bf16(float v, __nv_bfloat16& h, __nv_bfloat16& l) {
    h = __float2bfloat16_rn(v);
    l = __float2bfloat16_rn(v - __bfloat162float(h));
}

// ---------------- edge index access (int64 or int32, runtime-detected) ----
__device__ __forceinline__ int esrc(const void* ei, int e) {
    return g_is64 ? (int)((const long long*)ei)[e] : ((const int*)ei)[e];
}
__device__ __forceinline__ int edst(const void* ei, int e) {
    return g_is64 ? (int)((const long long*)ei)[(size_t)N_EDGES + e]
                  : ((const int*)ei)[(size_t)N_EDGES + e];
}

// init degrees; block 0 also detects int64-vs-int32 edge dtype
__global__ void k_init(const int* ei) {
    int i = blockIdx.x * blockDim.x + threadIdx.x;
    if (i < N_NODES) g_deg[i] = 0;
    if (blockIdx.x == 0) {
        bool ok = true;
        for (int j = threadIdx.x; j < 4096; j += blockDim.x)
            if (ei[2 * j + 1] != 0) ok = false;
        int all = __syncthreads_and((int)ok);
        if (threadIdx.x == 0) g_is64 = all ? 1 : 0;
    }
}
__global__ void k_hist(const void* ei) {
    int e = blockIdx.x * blockDim.x + threadIdx.x;
    if (e < N_EDGES) atomicAdd(&g_deg[edst(ei, e)], 1);
}
__global__ void k_scan_block() {
    __shared__ int s[SCAN_B];
    int i = blockIdx.x * SCAN_B + threadIdx.x;
    int v = (i < N_NODES) ? g_deg[i] : 0;
    s[threadIdx.x] = v;
    __syncthreads();
    for (int off = 1; off < SCAN_B; off <<= 1) {
        int t = (threadIdx.x >= off) ? s[threadIdx.x - off] : 0;
        __syncthreads();
        s[threadIdx.x] += t;
        __syncthreads();
    }
    if (i < N_NODES) g_rowptr[i] = s[threadIdx.x] - v;
    if (threadIdx.x == SCAN_B - 1) g_part[blockIdx.x] = s[SCAN_B - 1];
}
__global__ void k_scan_part() {
    __shared__ int s[256];
    int t = threadIdx.x;
    int v = (t < SCAN_NB) ? g_part[t] : 0;
    s[t] = v;
    __syncthreads();
    for (int off = 1; off < 256; off <<= 1) {
        int u = (t >= off) ? s[t - off] : 0;
        __syncthreads();
        s[t] += u;
        __syncthreads();
    }
    if (t < SCAN_NB) g_part[t] = s[t] - v;
}
__global__ void k_scan_add() {
    int i = blockIdx.x * blockDim.x + threadIdx.x;
    if (i < N_NODES) {
        int r = g_rowptr[i] + g_part[i / SCAN_B];
        g_rowptr[i] = r;
        g_fill[i] = r;
    }
    if (i == 0) g_rowptr[N_NODES] = N_EDGES;
}
__global__ void k_scatter(const void* ei) {
    int e = blockIdx.x * blockDim.x + threadIdx.x;
    if (e < N_EDGES) {
        int d = edst(ei, e);
        int p = atomicAdd(&g_fill[d], 1);
        g_col[p] = esrc(ei, e);
    }
}

// ---------------- weight conversion (both layers, split-2 bf16) ----------
__global__ void k_conv_w(const float* __restrict__ W1l, const float* __restrict__ W1r,
                         const float* __restrict__ W2l, const float* __restrict__ W2r) {
    int idx = blockIdx.x * blockDim.x + threadIdx.x;
    int tot1 = DHID * 64;
    if (idx < tot1) {
        int o = idx >> 6, q = idx & 63;
        int c = 2 * q;
        float v0 = (c < 64) ? W1l[o * 64 + c] : W1r[o * 64 + c - 64];
        float v1 = (c < 64) ? W1l[o * 64 + c + 1] : W1r[o * 64 + c - 63];
        __nv_bfloat16 h0, h1, l0, l1;
        split_bf16(v0, h0, l0); split_bf16(v1, h1, l1);
        __nv_bfloat162 ph = __nv_bfloat162(h0, h1);
        __nv_bfloat162 pl = __nv_bfloat162(l0, l1);
        g_w1h[idx] = *(uint32_t*)&ph;
        g_w1l[idx] = *(uint32_t*)&pl;
    } else if (idx < tot1 + W2ROWS * 64) {
        int j = idx - tot1;
        int o = j >> 6, q = j & 63;
        int c = 2 * q;
        float v0 = (o < DOUT) ? W2l[o * DHID + c] : W2r[(o - DOUT) * DHID + c];
        float v1 = (o < DOUT) ? W2l[o * DHID + c + 1] : W2r[(o - DOUT) * DHID + c + 1];
        __nv_bfloat16 h0, h1, l0, l1;
        split_bf16(v0, h0, l0); split_bf16(v1, h1, l1);
        __nv_bfloat162 ph = __nv_bfloat162(h0, h1);
        __nv_bfloat162 pl = __nv_bfloat162(l0, l1);
        g_w2h[j] = *(uint32_t*)&ph;
        g_w2l[j] = *(uint32_t*)&pl;
    }
}

// ---------------- fused: aggregate + GEMM1 + relu + GEMM2 -----------------
// Per CTA: 128 nodes. A/h1 tiles live entirely in SMEM (no global round-trip).
__global__ void __launch_bounds__(512) k_fused(const float* __restrict__ x,
                                               const float* __restrict__ b1) {
    extern __shared__ char dsm[];
    __nv_bfloat16* sAh = (__nv_bfloat16*)(dsm + SM_AH);
    __nv_bfloat16* sAl = (__nv_bfloat16*)(dsm + SM_AL);
    __nv_bfloat16* sW1h = (__nv_bfloat16*)(dsm + SM_W1H);
    __nv_bfloat16* sW1l = (__nv_bfloat16*)(dsm + SM_W1L);
    __nv_bfloat16* sW2h = (__nv_bfloat16*)(dsm + SM_W2H);
    __nv_bfloat16* sW2l = (__nv_bfloat16*)(dsm + SM_W2L);
    float* sB = (float*)(dsm + SM_BIAS);

    int tid = threadIdx.x, wid = tid >> 5, lane = tid & 31;
    int base = blockIdx.x * TILE_M;

    // ---- stage weights (pre-split bf16 in global) ----
    for (int i = tid; i < 128 * 16; i += 512) {
        int r = i >> 4, c8 = i & 15;
        *(uint4*)((char*)sW1h + r * (LDS_ROW * 2) + c8 * 16) = *(const uint4*)(g_w1h + r * 64 + c8 * 4);
        *(uint4*)((char*)sW1l + r * (LDS_ROW * 2) + c8 * 16) = *(const uint4*)(g_w1l + r * 64 + c8 * 4);
    }
    for (int i = tid; i < W2ROWS * 16; i += 512) {
        int r = i >> 4, c8 = i & 15;
        *(uint4*)((char*)sW2h + r * (LDS_ROW * 2) + c8 * 16) = *(const uint4*)(g_w2h + r * 64 + c8 * 4);
        *(uint4*)((char*)sW2l + r * (LDS_ROW * 2) + c8 * 16) = *(const uint4*)(g_w2l + r * 64 + c8 * 4);
    }
    if (tid < DHID) sB[tid] = b1[tid];

    // ---- gather-aggregate + self rows -> split into sAh/sAl ----
    // warp w handles rows w*8 .. w*8+7; lane covers cols (lane, lane+32)
#pragma unroll 1
    for (int i = 0; i < 8; i++) {
        int r = wid * 8 + i;
        int n = base + r;
        float a0 = 0.f, a1 = 0.f, c0 = 0.f, c1 = 0.f;
        float s0v = 0.f, s1v = 0.f;
        float inv = 1.f;
        if (n < N_NODES) {
            int s0 = g_rowptr[n], s1 = g_rowptr[n + 1];
            int e = s0;
            for (; e + 1 < s1; e += 2) {
                const float* f0 = x + (size_t)g_col[e] * DIN;
                const float* f1 = x + (size_t)g_col[e + 1] * DIN;
                a0 += f0[lane]; a1 += f0[lane + 32];
                c0 += f1[lane]; c1 += f1[lane + 32];
            }
            if (e < s1) {
                const float* f0 = x + (size_t)g_col[e] * DIN;
                a0 += f0[lane]; a1 += f0[lane + 32];
            }
            a0 += c0; a1 += c1;
            inv = 1.f / (float)max(s1 - s0, 1);
            s0v = x[(size_t)n * DIN + lane];
            s1v = x[(size_t)n * DIN + 32 + lane];
        }
        a0 *= inv; a1 *= inv;
        __nv_bfloat16 h, l;
        split_bf16(a0, h, l);
        sAh[r * LDS_ROW + lane] = h; sAl[r * LDS_ROW + lane] = l;
        split_bf16(a1, h, l);
        sAh[r * LDS_ROW + lane + 32] = h; sAl[r * LDS_ROW + lane + 32] = l;
        split_bf16(s0v, h, l);
        sAh[r * LDS_ROW + 64 + lane] = h; sAl[r * LDS_ROW + 64 + lane] = l;
        split_bf16(s1v, h, l);
        sAh[r * LDS_ROW + 96 + lane] = h; sAl[r * LDS_ROW + 96 + lane] = l;
    }
    __syncthreads();

    // ---- GEMM1: 128x128, warp grid 4(M) x 4(N), warp tile 32x32 ----
    int Rb = (wid & 3) * 32;
    int Nb = (wid >> 2) * 32;
    int qr = lane >> 2;
    int qc = 2 * (lane & 3);

    float acc[2][4][4];
#pragma unroll
    for (int mt = 0; mt < 2; mt++)
#pragma unroll
        for (int nt = 0; nt < 4; nt++)
#pragma unroll
            for (int j = 0; j < 4; j++) acc[mt][nt][j] = 0.f;

    for (int ks = 0; ks < 8; ks++) {
        int kc = ks * 16 + qc;
        uint32_t ah[2][4], al[2][4];
#pragma unroll
        for (int mt = 0; mt < 2; mt++) {
            int r = Rb + mt * 16 + qr;
            ah[mt][0] = *(const uint32_t*)(sAh + r * LDS_ROW + kc);
            ah[mt][1] = *(const uint32_t*)(sAh + (r + 8) * LDS_ROW + kc);
            ah[mt][2] = *(const uint32_t*)(sAh + r * LDS_ROW + kc + 8);
            ah[mt][3] = *(const uint32_t*)(sAh + (r + 8) * LDS_ROW + kc + 8);
            al[mt][0] = *(const uint32_t*)(sAl + r * LDS_ROW + kc);
            al[mt][1] = *(const uint32_t*)(sAl + (r + 8) * LDS_ROW + kc);
            al[mt][2] = *(const uint32_t*)(sAl + r * LDS_ROW + kc + 8);
            al[mt][3] = *(const uint32_t*)(sAl + (r + 8) * LDS_ROW + kc + 8);
        }
#pragma unroll
        for (int nt = 0; nt < 4; nt++) {
            int nn = Nb + nt * 8 + qr;
            uint32_t bh0 = *(const uint32_t*)(sW1h + nn * LDS_ROW + kc);
            uint32_t bh1 = *(const uint32_t*)(sW1h + nn * LDS_ROW + kc + 8);
            uint32_t bl0 = *(const uint32_t*)(sW1l + nn * LDS_ROW + kc);
            uint32_t bl1 = *(const uint32_t*)(sW1l + nn * LDS_ROW + kc + 8);
#pragma unroll
            for (int mt = 0; mt < 2; mt++) {
                mma16816(acc[mt][nt], ah[mt], bh0, bh1);
                mma16816(acc[mt][nt], al[mt], bh0, bh1);
                mma16816(acc[mt][nt], ah[mt], bl0, bl1);
            }
        }
    }
    __syncthreads();  // done reading A; safe to overwrite with h1

    // ---- epilogue 1: bias + relu + resplit -> sAh/sAl (h1 tile) ----
#pragma unroll
    for (int mt = 0; mt < 2; mt++) {
#pragma unroll
        for (int nt = 0; nt < 4; nt++) {
            int c = Nb + nt * 8 + qc;
            float bv0 = sB[c], bv1 = sB[c + 1];
#pragma unroll
            for (int half = 0; half < 2; half++) {
                int r = Rb + mt * 16 + qr + half * 8;
                float v0 = acc[mt][nt][2 * half] + bv0;
                float v1 = acc[mt][nt][2 * half + 1] + bv1;
                v0 = v0 > 0.f ? v0 : 0.f;
                v1 = v1 > 0.f ? v1 : 0.f;
                __nv_bfloat16 h0, h1, l0, l1;
                split_bf16(v0, h0, l0);
                split_bf16(v1, h1, l1);
                __nv_bfloat162 ph = __nv_bfloat162(h0, h1);
                __nv_bfloat162 pl = __nv_bfloat162(l0, l1);
                *(uint32_t*)(sAh + r * LDS_ROW + c) = *(uint32_t*)&ph;
                *(uint32_t*)(sAl + r * LDS_ROW + c) = *(uint32_t*)&pl;
            }
        }
    }
    __syncthreads();

    // ---- GEMM2: 128x80, warp grid 8(M) x 2(N), warp tile 16x40 ----
    int Rb2 = (wid & 7) * 16;
    int Nb2 = (wid >> 3) * 40;

    float acc2[5][4];
#pragma unroll
    for (int nt = 0; nt < 5; nt++)
#pragma unroll
        for (int j = 0; j < 4; j++) acc2[nt][j] = 0.f;

    for (int ks = 0; ks < 8; ks++) {
        int kc = ks * 16 + qc;
        int r = Rb2 + qr;
        uint32_t ah[4], al[4];
        ah[0] = *(const uint32_t*)(sAh + r * LDS_ROW + kc);
        ah[1] = *(const uint32_t*)(sAh + (r + 8) * LDS_ROW + kc);
        ah[2] = *(const uint32_t*)(sAh + r * LDS_ROW + kc + 8);
        ah[3] = *(const uint32_t*)(sAh + (r + 8) * LDS_ROW + kc + 8);
        al[0] = *(const uint32_t*)(sAl + r * LDS_ROW + kc);
        al[1] = *(const uint32_t*)(sAl + (r + 8) * LDS_ROW + kc);
        al[2] = *(const uint32_t*)(sAl + r * LDS_ROW + kc + 8);
        al[3] = *(const uint32_t*)(sAl + (r + 8) * LDS_ROW + kc + 8);
#pragma unroll
        for (int nt = 0; nt < 5; nt++) {
            int nn = Nb2 + nt * 8 + qr;
            uint32_t bh0 = *(const uint32_t*)(sW2h + nn * LDS_ROW + kc);
            uint32_t bh1 = *(const uint32_t*)(sW2h + nn * LDS_ROW + kc + 8);
            uint32_t bl0 = *(const uint32_t*)(sW2l + nn * LDS_ROW + kc);
            uint32_t bl1 = *(const uint32_t*)(sW2l + nn * LDS_ROW + kc + 8);
            mma16816(acc2[nt], ah, bh0, bh1);
            mma16816(acc2[nt], al, bh0, bh1);
            mma16816(acc2[nt], ah, bl0, bl1);
        }
    }

    // ---- epilogue 2: write y2l / y2r ----
#pragma unroll
    for (int nt = 0; nt < 5; nt++) {
        int c = Nb2 + nt * 8 + qc;  // 0..78 even
        float* dst = (c < DOUT) ? g_y2l : g_y2r;
        int cc = (c < DOUT) ? c : c - DOUT;
        int n0 = base + Rb2 + qr;
        if (n0 < N_NODES)
            *(float2*)&dst[(size_t)n0 * DOUT + cc] = make_float2(acc2[nt][0], acc2[nt][1]);
        int n1 = n0 + 8;
        if (n1 < N_NODES)
            *(float2*)&dst[(size_t)n1 * DOUT + cc] = make_float2(acc2[nt][2], acc2[nt][3]);
    }
}

// ---------------- final: out = log_softmax(mean-agg(y2l) + b2 + y2r) ------
__global__ void k_out(const float* __restrict__ b2, float* __restrict__ out) {
    int warp = (blockIdx.x * blockDim.x + threadIdx.x) >> 5;
    int lane = threadIdx.x & 31;
    if (warp >= N_NODES) return;
    float a0 = 0.f, a1 = 0.f, c0 = 0.f, c1 = 0.f;
    int s0 = g_rowptr[warp], s1 = g_rowptr[warp + 1];
    int e = s0;
    for (; e + 1 < s1; e += 2) {
        const float* f0 = g_y2l + (size_t)g_col[e] * DOUT;
        const float* f1 = g_y2l + (size_t)g_col[e + 1] * DOUT;
        a0 += f0[lane];
        c0 += f1[lane];
        if (lane < 8) { a1 += f0[32 + lane]; c1 += f1[32 + lane]; }
    }
    if (e < s1) {
        const float* f0 = g_y2l + (size_t)g_col[e] * DOUT;
        a0 += f0[lane];
        if (lane < 8) a1 += f0[32 + lane];
    }
    a0 += c0; a1 += c1;
    float inv = 1.f / (float)max(s1 - s0, 1);
    size_t nb = (size_t)warp * DOUT;
    float v0 = a0 * inv + b2[lane] + g_y2r[nb + lane];
    float v1 = (lane < 8) ? (a1 * inv + b2[32 + lane] + g_y2r[nb + 32 + lane])
                          : -INFINITY;
    float m = fmaxf(v0, v1);
    for (int off = 16; off; off >>= 1)
        m = fmaxf(m, __shfl_xor_sync(0xffffffffu, m, off));
    float s = expf(v0 - m) + ((lane < 8) ? expf(v1 - m) : 0.f);
    for (int off = 16; off; off >>= 1)
        s += __shfl_xor_sync(0xffffffffu, s, off);
    float lse = m + logf(s);
    out[nb + lane] = v0 - lse;
    if (lane < 8) out[nb + 32 + lane] = v1 - lse;
}

// ---------------- launch --------------------------------------------------
extern "C" void kernel_launch(void* const* d_in, const int* in_sizes, int n_in,
                              void* d_out, int out_size) {
    const float* x = (const float*)d_in[0];
    const void* ei = d_in[1];
    const float* W1l = (const float*)d_in[2];
    const float* b1 = (const float*)d_in[3];
    const float* W1r = (const float*)d_in[4];
    const float* W2l = (const float*)d_in[5];
    const float* b2 = (const float*)d_in[6];
    const float* W2r = (const float*)d_in[7];
    float* out = (float*)d_out;

    cudaFuncSetAttribute(k_fused, cudaFuncAttributeMaxDynamicSharedMemorySize,
                         SM_TOTAL);

    k_init<<<(N_NODES + 255) / 256, 256>>>((const int*)ei);
    k_conv_w<<<((DHID * 64 + W2ROWS * 64) + 255) / 256, 256>>>(W1l, W1r, W2l, W2r);
    k_hist<<<(N_EDGES + 255) / 256, 256>>>(ei);
    k_scan_block<<<SCAN_NB, SCAN_B>>>();
    k_scan_part<<<1, 256>>>();
    k_scan_add<<<(N_NODES + 255) / 256, 256>>>();
    k_scatter<<<(N_EDGES + 255) / 256, 256>>>(ei);

    k_fused<<<N_TILES, 512, SM_TOTAL>>>(x, b1);
    k_out<<<(N_NODES * 32 + 255) / 256, 256>>>(b2, out);
}